// round 11
// baseline (speedup 1.0000x reference)
#include <cuda_runtime.h>
#include <cuda_bf16.h>
#include <math_constants.h>

// CRF neg-log-likelihood, GB300 sm_103a.
// ONE WARP per batch row (64 CTAs x 32 threads), warp-synchronous exchange:
// no CTA barriers in the loop, only __syncwarp. Lane l<25 owns columns
// (2l, 2l+1). Partition stored SPLATTED in smem (word k = (p_k,p_k) bf162),
// so every LDS.128 word is directly an HFMA2 broadcast operand — splatting
// happens once at production (2 PRMT + STS.64 per lane). 50 HFMA2 into 8
// accumulators (depth 7). exp(feats) precomputed into smem as bf162 PAIRS
// (HMUL2 operand). Rescale by p[0] every 4 steps. Gold score in-warp;
// last CTA (atomic ticket) reduces the batch.

namespace {
constexpr int NTAG   = 50;
constexpr int TSTART = NTAG - 2;   // 48
constexpr int TSTOP  = NTAG - 1;   // 49
constexpr int BATCH  = 64;
constexpr int SEQ    = 512;
constexpr int NTHR   = 32;
constexpr int NPW    = 25;         // ef pair-words per step
constexpr int BUFW   = 52;         // splatted partition words (50 + 2 pad)
// dynamic smem: s_ef[(SEQ+1)*NPW] u32 pairs, then s_mask[SEQ+4]
constexpr int SMEM_EF_WORDS = (SEQ + 1) * NPW;
constexpr int SMEM_BYTES    = (SMEM_EF_WORDS + SEQ + 4) * 4;
}

__device__ float    g_partial[BATCH];
__device__ unsigned g_ticket = 0;

__device__ __forceinline__ float warpSumF(float v) {
#pragma unroll
    for (int o = 16; o > 0; o >>= 1) v += __shfl_xor_sync(0xffffffffu, v, o);
    return v;
}
__device__ __forceinline__ int warpSumI(int v) {
#pragma unroll
    for (int o = 16; o > 0; o >>= 1) v += __shfl_xor_sync(0xffffffffu, v, o);
    return v;
}
__device__ __forceinline__ __nv_bfloat162 u2b(unsigned u) {
    return *reinterpret_cast<__nv_bfloat162*>(&u);
}
__device__ __forceinline__ unsigned b2u(__nv_bfloat162 b) {
    return *reinterpret_cast<unsigned*>(&b);
}
__device__ __forceinline__ __nv_bfloat162 asbf2(float f) {
    return *reinterpret_cast<__nv_bfloat162*>(&f);
}
__device__ __forceinline__ unsigned splat_lo(unsigned a) {
    unsigned r; asm("prmt.b32 %0, %1, 0, 0x1010;" : "=r"(r) : "r"(a)); return r;
}
__device__ __forceinline__ unsigned splat_hi(unsigned a) {
    unsigned r; asm("prmt.b32 %0, %1, 0, 0x3232;" : "=r"(r) : "r"(a)); return r;
}

// GEMV: 50 HFMA2 over splatted words w[0..49] into 8 accumulators, tree-summed.
// Every operand word is already (p_k, p_k); et2[k] = (T[k][2l], T[k][2l+1]).
__device__ __forceinline__ __nv_bfloat162 gemv50(
    const float4 (&v)[13], const __nv_bfloat162 (&et2)[NTAG])
{
    __nv_bfloat162 z = __floats2bfloat162_rn(0.f, 0.f);
    __nv_bfloat162 a[8];
#pragma unroll
    for (int i = 0; i < 8; i++) a[i] = z;
#pragma unroll
    for (int k = 0; k < NTAG; k++) {
        float comp = (k % 4 == 0) ? v[k / 4].x :
                     (k % 4 == 1) ? v[k / 4].y :
                     (k % 4 == 2) ? v[k / 4].z : v[k / 4].w;
        a[k & 7] = __hfma2(asbf2(comp), et2[k], a[k & 7]);
    }
    a[0] = __hadd2(a[0], a[1]);
    a[2] = __hadd2(a[2], a[3]);
    a[4] = __hadd2(a[4], a[5]);
    a[6] = __hadd2(a[6], a[7]);
    a[0] = __hadd2(a[0], a[2]);
    a[4] = __hadd2(a[4], a[6]);
    return __hadd2(a[0], a[4]);
}

// One recursion step. On entry: efp = ef pair(t), m = mask[t]; exits with t+1 prefetched.
template <bool RESCALE>
__device__ __forceinline__ void fwd_step(
    int t, int l, bool act,
    const unsigned* __restrict__ src,   // 52-word splatted partition
    unsigned*       __restrict__ dst,
    const __nv_bfloat162 (&et2)[NTAG],
    unsigned& efp, int& m, unsigned& pju, float& offset,
    const unsigned* __restrict__ s_ef,
    const int*      __restrict__ s_mask,
    int lc)
{
    // 13 LDS.128 broadcast loads (issue first)
    float4 v[13];
#pragma unroll
    for (int q = 0; q < 13; q++) v[q] = ((const float4*)src)[q];

    float p0f = 1.f, rp0 = 1.f;
    if (RESCALE) {
        p0f = __uint_as_float(__float_as_uint(v[0].x) << 16);  // p[0]
        rp0 = __frcp_rn(p0f);                                  // off-path MUFU
    }

    __nv_bfloat162 s2 = gemv50(v, et2);
    unsigned q2u = b2u(__hmul2(s2, u2b(efp)));   // * (ef_2l, ef_2l+1)

    q2u = m ? q2u : pju;                         // masked: carry previous

    if (RESCALE)
        q2u = b2u(__hmul2(u2b(q2u), __float2bfloat162_rn(rp0)));

    pju = q2u;
    if (act) {
        uint2 st;                                 // splat-at-production
        st.x = splat_lo(q2u);                     // (q_2l,  q_2l)
        st.y = splat_hi(q2u);                     // (q_2l+1,q_2l+1)
        *(uint2*)(dst + 2 * l) = st;              // STS.64
    }

    // off-path prefetches for t+1
    efp = s_ef[(t + 1) * NPW + lc];
    m   = s_mask[t + 1];
    if (RESCALE) offset += __logf(p0f);

    __syncwarp();                                 // warp-local exchange fence
}

__global__ void __launch_bounds__(NTHR, 1)
crf_kernel(const float* __restrict__ feats,
           const int*   __restrict__ mask,
           const int*   __restrict__ tags,
           const float* __restrict__ trans,
           float*       __restrict__ out)
{
    const int b    = blockIdx.x;
    const int l    = threadIdx.x;
    const bool act = (l < NPW);
    const int lc   = act ? l : NPW - 1;

    extern __shared__ unsigned dyn[];
    unsigned* s_ef   = dyn;                           // [(SEQ+1)][NPW] ef pairs
    int*      s_mask = (int*)(dyn + SMEM_EF_WORDS);   // [SEQ+4]

    __shared__ __align__(16) unsigned spA[BUFW];
    __shared__ __align__(16) unsigned spB[BUFW];

    const float* fb = feats + (long long)b * SEQ * NTAG;
    const int*   mb = mask  + b * SEQ;
    const int*   tb = tags  + b * SEQ;

    // ---- prologue: mask + exp(feat) PAIRS into smem ----
    for (int t = l; t < SEQ; t += NTHR) s_mask[t] = mb[t];
    if (l < 4) s_mask[SEQ + l] = 0;
    // zero the guard row of s_ef (t = SEQ)
    if (l < NPW) s_ef[SEQ * NPW + l] = 0u;

#pragma unroll 4
    for (int idx = l; idx < SEQ * NPW; idx += NTHR) {
        int t = idx / NPW;
        int k = idx - t * NPW;
        float2 fv = *(const float2*)(fb + t * NTAG + 2 * k);
        s_ef[idx] = b2u(__floats2bfloat162_rn(__expf(fv.x), __expf(fv.y)));
    }

    // exp(transitions) for this lane's column pair
    __nv_bfloat162 et2[NTAG];
#pragma unroll
    for (int i = 0; i < NTAG; i++) {
        float e0 = act ? __expf(trans[i * NTAG + 2 * lc])     : 0.f;
        float e1 = act ? __expf(trans[i * NTAG + 2 * lc + 1]) : 0.f;
        et2[i] = __floats2bfloat162_rn(e0, e1);
    }

    // t = 0: normalize by partition0[tag 0]
    const float off0   = fb[0] + trans[TSTART * NTAG + 0];
    float       offset = off0;
    float2 f0 = *(const float2*)(fb + 2 * lc);
    float pa = __expf(f0.x + trans[TSTART * NTAG + 2 * lc]     - off0);
    float pb = __expf(f0.y + trans[TSTART * NTAG + 2 * lc + 1] - off0);
    unsigned pju = b2u(__floats2bfloat162_rn(pa, pb));
    if (act) {
        uint2 st;
        st.x = splat_lo(pju);
        st.y = splat_hi(pju);
        *(uint2*)(spA + 2 * l) = st;
    }
    if (l >= 2 * NPW && l < BUFW) { spA[l] = 0u; spB[l] = 0u; }  // pads 50,51
    __syncwarp();

    unsigned efp = s_ef[1 * NPW + lc];
    int      m   = s_mask[1];

    // t = 1..508 in groups of 4 (rescale on 4th), tail 509..511
    for (int t = 1; t + 3 < SEQ; t += 4) {
        fwd_step<false>(t,     l, act, spA, spB, et2, efp, m, pju, offset, s_ef, s_mask, lc);
        fwd_step<false>(t + 1, l, act, spB, spA, et2, efp, m, pju, offset, s_ef, s_mask, lc);
        fwd_step<false>(t + 2, l, act, spA, spB, et2, efp, m, pju, offset, s_ef, s_mask, lc);
        fwd_step<true >(t + 3, l, act, spB, spA, et2, efp, m, pju, offset, s_ef, s_mask, lc);
    }
    fwd_step<false>(SEQ - 3, l, act, spA, spB, et2, efp, m, pju, offset, s_ef, s_mask, lc);
    fwd_step<false>(SEQ - 2, l, act, spB, spA, et2, efp, m, pju, offset, s_ef, s_mask, lc);
    fwd_step<false>(SEQ - 1, l, act, spA, spB, et2, efp, m, pju, offset, s_ef, s_mask, lc);
    // final partition (splatted) lives in spB

    // terminal: s = P x exp(trans); column STOP=49 = high half of lane 24's pair
    float4 vf[13];
#pragma unroll
    for (int q = 0; q < 13; q++) vf[q] = ((const float4*)spB)[q];
    __nv_bfloat162 s2 = gemv50(vf, et2);
    unsigned su = __shfl_sync(0xffffffffu, b2u(s2), 24);
    float fwd = __logf(__high2float(u2b(su))) + offset;

    // ---- gold score (same warp) ----
    float acc = 0.f;
    int   len = 0;
#pragma unroll 4
    for (int t = l; t < SEQ; t += NTHR) {
        int tag  = tb[t];
        int prev = (t == 0) ? TSTART : tb[t - 1];
        int mm   = s_mask[t];
        if (mm) acc += fb[t * NTAG + tag] + trans[prev * NTAG + tag];
        len += mm;
    }
    acc = warpSumF(acc);
    len = warpSumI(len);

    unsigned lastflag = 0;
    if (l == 0) {
        int   endid = tb[len - 1];
        float gold  = acc + trans[endid * NTAG + TSTOP];
        g_partial[b] = fwd - gold;
        __threadfence();
        unsigned tk = atomicAdd(&g_ticket, 1u);
        lastflag = (tk == BATCH - 1) ? 1u : 0u;
    }
    lastflag = __shfl_sync(0xffffffffu, lastflag, 0);

    // last CTA out: reduce the 64 batch values, reset ticket (graph-replay safe)
    if (lastflag) {
        float v = ((volatile float*)g_partial)[l] + ((volatile float*)g_partial)[l + 32];
        v = warpSumF(v);
        if (l == 0) {
            out[0] = v;
            g_ticket = 0;
        }
    }
}

extern "C" void kernel_launch(void* const* d_in, const int* in_sizes, int n_in,
                              void* d_out, int out_size)
{
    const float* feats = (const float*)d_in[0];
    const int*   mask  = (const int*)d_in[1];
    const int*   tags  = (const int*)d_in[2];
    const float* trans = (const float*)d_in[3];
    float* out = (float*)d_out;

    cudaFuncSetAttribute(crf_kernel,
                         cudaFuncAttributeMaxDynamicSharedMemorySize, SMEM_BYTES);
    crf_kernel<<<BATCH, NTHR, SMEM_BYTES>>>(feats, mask, tags, trans, out);
}

// round 12
// speedup vs baseline: 1.5815x; 1.5815x over previous
#include <cuda_runtime.h>
#include <cuda_bf16.h>
#include <math_constants.h>

// CRF neg-log-likelihood, GB300 sm_103a.
// 64 CTAs x 64 threads (2 warps). R3/R10 skeleton: linear-space forward
// recursion, bf16 partition smem ping-pong, 25-pair HFMA2 GEMV, fp32 epilogue,
// rescale by p_prev[0] every 4 steps, exp(feats) precomputed into dynamic smem.
// NEW: per-row "mask all ones" fast path (no mask LDS, no SEL, no carry reg);
// masked rows use the general loop. Branch is once per CTA (uniform).

namespace {
constexpr int NTAG   = 50;
constexpr int TSTART = NTAG - 2;   // 48
constexpr int TSTOP  = NTAG - 1;   // 49
constexpr int BATCH  = 64;
constexpr int SEQ    = 512;
constexpr int NTHR   = 64;
constexpr int NPAIR  = 28;         // bf162 pairs (56 slots: 50 + 6 zero pad)
constexpr int SMEM_EF_WORDS = SEQ * NTAG;       // fp32 exp(feats), 102400 B
constexpr int SMEM_BYTES    = SMEM_EF_WORDS * 4;
}

__device__ float    g_partial[BATCH];
__device__ unsigned g_ticket = 0;

__device__ __forceinline__ float warpSumF(float v) {
#pragma unroll
    for (int o = 16; o > 0; o >>= 1) v += __shfl_xor_sync(0xffffffffu, v, o);
    return v;
}
__device__ __forceinline__ int warpSumI(int v) {
#pragma unroll
    for (int o = 16; o > 0; o >>= 1) v += __shfl_xor_sync(0xffffffffu, v, o);
    return v;
}
__device__ __forceinline__ __nv_bfloat162 asbf2(float f) {
    return *reinterpret_cast<__nv_bfloat162*>(&f);
}

// Shared GEMV core: 7 LDS.128 + 28 HFMA2 + tree. Returns fp32 sum; also p0.
__device__ __forceinline__ float gemv_core(
    const __nv_bfloat162* __restrict__ src,
    const __nv_bfloat162 (&et2)[NPAIR],
    float& p0f)
{
    const float4* sp4 = (const float4*)src;
    float4 v0 = sp4[0];
    float4 v1 = sp4[1];
    float4 v2 = sp4[2];
    float4 v3 = sp4[3];
    float4 v4 = sp4[4];
    float4 v5 = sp4[5];
    float4 v6 = sp4[6];

    p0f = __uint_as_float(__float_as_uint(v0.x) << 16);  // low bf16 of pair 0

    __nv_bfloat162 z  = __floats2bfloat162_rn(0.f, 0.f);
    __nv_bfloat162 a0 = z, a1 = z, a2 = z, a3 = z;

    a0 = __hfma2(asbf2(v0.x), et2[0],  a0);
    a1 = __hfma2(asbf2(v0.y), et2[1],  a1);
    a2 = __hfma2(asbf2(v0.z), et2[2],  a2);
    a3 = __hfma2(asbf2(v0.w), et2[3],  a3);
    a0 = __hfma2(asbf2(v1.x), et2[4],  a0);
    a1 = __hfma2(asbf2(v1.y), et2[5],  a1);
    a2 = __hfma2(asbf2(v1.z), et2[6],  a2);
    a3 = __hfma2(asbf2(v1.w), et2[7],  a3);
    a0 = __hfma2(asbf2(v2.x), et2[8],  a0);
    a1 = __hfma2(asbf2(v2.y), et2[9],  a1);
    a2 = __hfma2(asbf2(v2.z), et2[10], a2);
    a3 = __hfma2(asbf2(v2.w), et2[11], a3);
    a0 = __hfma2(asbf2(v3.x), et2[12], a0);
    a1 = __hfma2(asbf2(v3.y), et2[13], a1);
    a2 = __hfma2(asbf2(v3.z), et2[14], a2);
    a3 = __hfma2(asbf2(v3.w), et2[15], a3);
    a0 = __hfma2(asbf2(v4.x), et2[16], a0);
    a1 = __hfma2(asbf2(v4.y), et2[17], a1);
    a2 = __hfma2(asbf2(v4.z), et2[18], a2);
    a3 = __hfma2(asbf2(v4.w), et2[19], a3);
    a0 = __hfma2(asbf2(v5.x), et2[20], a0);
    a1 = __hfma2(asbf2(v5.y), et2[21], a1);
    a2 = __hfma2(asbf2(v5.z), et2[22], a2);
    a3 = __hfma2(asbf2(v5.w), et2[23], a3);
    a0 = __hfma2(asbf2(v6.x), et2[24], a0);
    a1 = __hfma2(asbf2(v6.y), et2[25], a1);
    a2 = __hfma2(asbf2(v6.z), et2[26], a2);
    a3 = __hfma2(asbf2(v6.w), et2[27], a3);

    a0 = __hadd2(a0, a1);
    a2 = __hadd2(a2, a3);
    a0 = __hadd2(a0, a2);
    float2 sf = __bfloat1622float2(a0);
    return sf.x + sf.y;
}

// FAST step: mask known to be 1. No SEL, no carry register, no mask LDS.
template <bool RESCALE>
__device__ __forceinline__ void fwd_step_fast(
    int t, int j, int jf, bool act,
    const __nv_bfloat162* __restrict__ src,
    __nv_bfloat162*       __restrict__ dst,
    const __nv_bfloat162 (&et2)[NPAIR],
    float& ef, float& offset,
    const float* __restrict__ s_ef)
{
    float p0f;
    float s = gemv_core(src, et2, p0f);
    float rp0 = 1.f;
    if (RESCALE) rp0 = __frcp_rn(p0f);

    float q = s * ef;
    if (RESCALE) q *= rp0;

    if (act) ((__nv_bfloat16*)dst)[j] = __float2bfloat16(q);

    ef = s_ef[(t + 1) * NTAG + jf];     // off-path prefetch
    if (RESCALE) offset += __logf(p0f);

    __syncthreads();
}

// GENERAL step: honors mask (carry previous partition on masked steps).
template <bool RESCALE>
__device__ __forceinline__ void fwd_step_gen(
    int t, int j, int jf, bool act,
    const __nv_bfloat162* __restrict__ src,
    __nv_bfloat162*       __restrict__ dst,
    const __nv_bfloat162 (&et2)[NPAIR],
    float& ef, float& pj, float& offset, int& m,
    const float* __restrict__ s_ef,
    const int*   __restrict__ s_mask)
{
    float p0f;
    float s = gemv_core(src, et2, p0f);
    float rp0 = 1.f;
    if (RESCALE) rp0 = __frcp_rn(p0f);

    float q = s * ef;
    q = m ? q : pj;
    if (RESCALE) q *= rp0;
    pj = q;

    if (act) ((__nv_bfloat16*)dst)[j] = __float2bfloat16(q);

    ef = s_ef[(t + 1) * NTAG + jf];
    m  = s_mask[t + 1];
    if (RESCALE) offset += __logf(p0f);

    __syncthreads();
}

__global__ void __launch_bounds__(NTHR, 1)
crf_kernel(const float* __restrict__ feats,
           const int*   __restrict__ mask,
           const int*   __restrict__ tags,
           const float* __restrict__ trans,
           float*       __restrict__ out)
{
    const int b    = blockIdx.x;
    const int j    = threadIdx.x;
    const int jf   = min(j, NTAG - 1);
    const int lane = j & 31;
    const int wid  = j >> 5;
    const bool act = (j < NTAG);

    extern __shared__ float s_ef[];          // [SEQ][NTAG] fp32 exp(feats)

    __shared__ __align__(16) __nv_bfloat162 spA[NPAIR];
    __shared__ __align__(16) __nv_bfloat162 spB[NPAIR];
    __shared__ float s_fwd;
    __shared__ float s_acc[2];
    __shared__ int   s_len[2];
    __shared__ int   s_mask[SEQ + 1];
    __shared__ int   s_ones[2];
    __shared__ bool  s_last;
    __shared__ float s_red2[2];

    const float* fb = feats + (long long)b * SEQ * NTAG;
    const int*   mb = mask  + b * SEQ;
    const int*   tb = tags  + b * SEQ;

    // ---- prologue: mask + all-ones check + exp(feats) into smem ----
    {
        int cnt = 0;
        for (int t = j; t < SEQ; t += NTHR) { int v = mb[t]; s_mask[t] = v; cnt += v; }
        cnt = warpSumI(cnt);
        if (lane == 0) s_ones[wid] = cnt;
        if (j == 0) s_mask[SEQ] = 0;
    }
    {
        const float4* f4 = (const float4*)fb;    // 6400 float4
#pragma unroll 4
        for (int idx = j; idx < SEQ * NTAG / 4; idx += NTHR) {
            float4 v = f4[idx];
            float4 e;
            e.x = __expf(v.x);
            e.y = __expf(v.y);
            e.z = __expf(v.z);
            e.w = __expf(v.w);
            ((float4*)s_ef)[idx] = e;
        }
    }

    // exp(transitions) column j as bf162 pairs (thread j owns next-tag j)
    __nv_bfloat162 et2[NPAIR];
#pragma unroll
    for (int k = 0; k < NPAIR; k++) et2[k] = __floats2bfloat162_rn(0.f, 0.f);
    if (act) {
#pragma unroll
        for (int k = 0; k < 25; k++) {
            float e0 = __expf(trans[(2 * k)     * NTAG + j]);
            float e1 = __expf(trans[(2 * k + 1) * NTAG + j]);
            et2[k] = __floats2bfloat162_rn(e0, e1);
        }
    }

    // t = 0: normalize by partition0[tag 0]
    const float off0   = fb[0] + trans[TSTART * NTAG + 0];
    float       offset = off0;
    float pj = 0.f;
    if (act) pj = __expf(fb[j] + trans[TSTART * NTAG + j] - off0);
    if (j < 2 * NPAIR) {
        ((__nv_bfloat16*)spA)[j] = __float2bfloat16(act ? pj : 0.f);
        ((__nv_bfloat16*)spB)[j] = __float2bfloat16(0.f);   // zero pads once
    }
    __syncthreads();                        // covers prologue writes

    const bool allOnes = (s_ones[0] + s_ones[1]) == SEQ;   // uniform across CTA
    float ef = s_ef[1 * NTAG + jf];

    if (allOnes) {
        // ---------------- fast path: no mask machinery ----------------
        for (int t = 1; t + 3 < SEQ; t += 4) {
            fwd_step_fast<false>(t,     j, jf, act, spA, spB, et2, ef, offset, s_ef);
            fwd_step_fast<false>(t + 1, j, jf, act, spB, spA, et2, ef, offset, s_ef);
            fwd_step_fast<false>(t + 2, j, jf, act, spA, spB, et2, ef, offset, s_ef);
            fwd_step_fast<true >(t + 3, j, jf, act, spB, spA, et2, ef, offset, s_ef);
        }
        fwd_step_fast<false>(SEQ - 3, j, jf, act, spA, spB, et2, ef, offset, s_ef);
        fwd_step_fast<false>(SEQ - 2, j, jf, act, spB, spA, et2, ef, offset, s_ef);
        {   // final step inline (no ef prefetch)
            float p0f;
            float s = gemv_core(spA, et2, p0f);
            float q = s * ef;
            if (act) ((__nv_bfloat16*)spB)[j] = __float2bfloat16(q);
            __syncthreads();
        }
    } else {
        // ---------------- general path: honors mask ----------------
        int m = s_mask[1];
        for (int t = 1; t + 3 < SEQ; t += 4) {
            fwd_step_gen<false>(t,     j, jf, act, spA, spB, et2, ef, pj, offset, m, s_ef, s_mask);
            fwd_step_gen<false>(t + 1, j, jf, act, spB, spA, et2, ef, pj, offset, m, s_ef, s_mask);
            fwd_step_gen<false>(t + 2, j, jf, act, spA, spB, et2, ef, pj, offset, m, s_ef, s_mask);
            fwd_step_gen<true >(t + 3, j, jf, act, spB, spA, et2, ef, pj, offset, m, s_ef, s_mask);
        }
        fwd_step_gen<false>(SEQ - 3, j, jf, act, spA, spB, et2, ef, pj, offset, m, s_ef, s_mask);
        fwd_step_gen<false>(SEQ - 2, j, jf, act, spB, spA, et2, ef, pj, offset, m, s_ef, s_mask);
        {   // final step inline
            float p0f;
            float s = gemv_core(spA, et2, p0f);
            float q = s * ef;
            q = m ? q : pj;
            if (act) ((__nv_bfloat16*)spB)[j] = __float2bfloat16(q);
            __syncthreads();
        }
    }
    // final partition lives in spB

    // terminal: forward = log( sum_i p[i] * exp(trans[i,STOP]) ) + offset
    if (j == TSTOP) {
        float p0f;
        float s = gemv_core(spB, et2, p0f);
        s_fwd = __logf(s) + offset;
    }

    // ---- gold score (all 64 threads) ----
    float acc = 0.f;
    int   len = 0;
#pragma unroll
    for (int t = j; t < SEQ; t += NTHR) {
        int tag  = tb[t];
        int prev = (t == 0) ? TSTART : tb[t - 1];
        int mm   = s_mask[t];
        if (mm) acc += fb[t * NTAG + tag] + trans[prev * NTAG + tag];
        len += mm;
    }
    acc = warpSumF(acc);
    len = warpSumI(len);
    if (lane == 0) { s_acc[wid] = acc; s_len[wid] = len; }
    __syncthreads();

    if (j == 0) {
        int   L     = s_len[0] + s_len[1];
        int   endid = tb[L - 1];
        float gold  = s_acc[0] + s_acc[1] + trans[endid * NTAG + TSTOP];
        g_partial[b] = s_fwd - gold;
        __threadfence();
        unsigned tk = atomicAdd(&g_ticket, 1u);
        s_last = (tk == BATCH - 1);
    }
    __syncthreads();

    // last CTA out: reduce all 64 batch values, reset ticket (graph-replay safe)
    if (s_last) {
        float v = ((volatile float*)g_partial)[j];
        v = warpSumF(v);
        if (lane == 0) s_red2[wid] = v;
        __syncthreads();
        if (j == 0) {
            out[0] = s_red2[0] + s_red2[1];
            g_ticket = 0;
        }
    }
}

extern "C" void kernel_launch(void* const* d_in, const int* in_sizes, int n_in,
                              void* d_out, int out_size)
{
    const float* feats = (const float*)d_in[0];
    const int*   mask  = (const int*)d_in[1];
    const int*   tags  = (const int*)d_in[2];
    const float* trans = (const float*)d_in[3];
    float* out = (float*)d_out;

    cudaFuncSetAttribute(crf_kernel,
                         cudaFuncAttributeMaxDynamicSharedMemorySize, SMEM_BYTES);
    crf_kernel<<<BATCH, NTHR, SMEM_BYTES>>>(feats, mask, tags, trans, out);
}